// round 4
// baseline (speedup 1.0000x reference)
#include <cuda_runtime.h>
#include <math.h>

// Geometry: 64 images of 512*512*3 = 786432 floats (3 MB each)
#define N_IMG 64
#define IMG_ELEMS 786432
#define IMG_VEC4 196608                  // IMG_ELEMS/4
#define IMGS_PER_BATCH 32                // 96 MB batch < 126 MB L2
#define N_BATCH 2
#define CHUNKS 16
#define NBLK (IMGS_PER_BATCH * CHUNKS)   // 512 blocks, all co-resident at 4/SM
#define CHUNK_VEC4 (IMG_VEC4 / CHUNKS)   // 12288 float4 = 192 KB
#define THREADS 256

// Persistent device scratch
__device__ float2 g_partials[N_IMG][CHUNKS];
__device__ float2 g_ss[N_IMG];           // (scale, shift)
__device__ int    g_bar[4];              // self-resetting grid barriers

__device__ __forceinline__ int ld_acq(const int* p) {
    int v;
    asm volatile("ld.acquire.gpu.s32 %0, [%1];" : "=r"(v) : "l"(p) : "memory");
    return v;
}

// Up-down barrier: arrive, spin to NBLK, depart; last departer resets to 0.
// Safe across graph replays (counter returns to 0 before kernel exit).
__device__ __forceinline__ void grid_sync(int id) {
    __syncthreads();
    if (threadIdx.x == 0) {
        __threadfence();
        atomicAdd(&g_bar[id], 1);
        while (ld_acq(&g_bar[id]) < NBLK) { }
        int old = atomicAdd(&g_bar[id], 1);
        if (old == 2 * NBLK - 1) g_bar[id] = 0;   // all departed; no one reads again
    }
    __syncthreads();
}

__global__ __launch_bounds__(THREADS, 4)
void fused_l2_kernel(const float4* __restrict__ in, float4* __restrict__ out) {
    __shared__ float2 warp_red[THREADS / 32];
    __shared__ float2 sh_ss;

    const int blk  = blockIdx.x;
    const int ib   = blk >> 4;            // image within batch (0..31)
    const int c    = blk & 15;            // chunk (0..15)
    const int tid  = threadIdx.x;
    const int lane = tid & 31, wid = tid >> 5;

    #pragma unroll 1
    for (int b = 0; b < N_BATCH; ++b) {
        const int img = b * IMGS_PER_BATCH + ib;
        const size_t base = (size_t)img * IMG_VEC4 + (size_t)c * CHUNK_VEC4;

        // ---- Pass A: read + reduce (fills L2) ----
        {
            float s = 0.f, sq = 0.f;
            #pragma unroll 4
            for (int j = tid; j < CHUNK_VEC4; j += THREADS) {
                float4 v = __ldcg(in + base + j);
                s  += (v.x + v.y) + (v.z + v.w);
                sq += (v.x * v.x + v.y * v.y) + (v.z * v.z + v.w * v.w);
            }
            #pragma unroll
            for (int off = 16; off > 0; off >>= 1) {
                s  += __shfl_down_sync(0xffffffffu, s,  off);
                sq += __shfl_down_sync(0xffffffffu, sq, off);
            }
            if (lane == 0) warp_red[wid] = make_float2(s, sq);
            __syncthreads();
            if (wid == 0) {
                float2 v = (lane < THREADS / 32) ? warp_red[lane] : make_float2(0.f, 0.f);
                s = v.x; sq = v.y;
                #pragma unroll
                for (int off = 4; off > 0; off >>= 1) {
                    s  += __shfl_down_sync(0xffffffffu, s,  off);
                    sq += __shfl_down_sync(0xffffffffu, sq, off);
                }
                if (lane == 0) g_partials[img][c] = make_float2(s, sq);
            }
        }

        grid_sync(2 * b);                 // partials of this batch visible

        // ---- Finalize: one warp per image, fixed order (deterministic) ----
        if (blk < IMGS_PER_BATCH && wid == 0) {
            const int fimg = b * IMGS_PER_BATCH + blk;
            float s = 0.f, sq = 0.f;
            if (lane < CHUNKS) {
                float2 p = g_partials[fimg][lane];
                s = p.x; sq = p.y;
            }
            // deterministic tree over 16 lanes
            #pragma unroll
            for (int off = 8; off > 0; off >>= 1) {
                s  += __shfl_down_sync(0xffffffffu, s,  off);
                sq += __shfl_down_sync(0xffffffffu, sq, off);
            }
            if (lane == 0) {
                const float inv_n = 1.0f / (float)IMG_ELEMS;
                float mean = s * inv_n;
                float var  = sq * inv_n - mean * mean;
                float stddev = sqrtf(fmaxf(var, 0.0f));
                const float min_std = 1.0f / sqrtf((float)IMG_ELEMS);
                float scale = 1.0f / fmaxf(stddev, min_std);
                g_ss[fimg] = make_float2(scale, -mean * scale);
            }
        }

        grid_sync(2 * b + 1);             // scale/shift visible

        if (tid == 0) sh_ss = g_ss[img];
        __syncthreads();
        const float scale = sh_ss.x, shift = sh_ss.y;

        // ---- Pass B: apply (reads mostly from L2, streaming writes) ----
        // No barrier after this: next batch's pass A overlaps with these writes.
        #pragma unroll 4
        for (int j = tid; j < CHUNK_VEC4; j += THREADS) {
            float4 v = __ldcg(in + base + j);
            float4 r;
            r.x = fmaf(v.x, scale, shift);
            r.y = fmaf(v.y, scale, shift);
            r.z = fmaf(v.z, scale, shift);
            r.w = fmaf(v.w, scale, shift);
            __stcs(out + base + j, r);
        }
    }
}

extern "C" void kernel_launch(void* const* d_in, const int* in_sizes, int n_in,
                              void* d_out, int out_size) {
    const float4* in = (const float4*)d_in[0];
    float4* out = (float4*)d_out;
    fused_l2_kernel<<<NBLK, THREADS>>>(in, out);
}

// round 5
// speedup vs baseline: 1.2944x; 1.2944x over previous
#include <cuda_runtime.h>
#include <math.h>

// Geometry: 64 images of 512*512*3 = 786432 floats (3 MB each)
#define N_IMG 64
#define IMG_ELEMS 786432
#define IMG_VEC4  196608               // IMG_ELEMS / 4
#define BLOCKS_PER_IMG 24
#define CHUNK_VEC4 (IMG_VEC4 / BLOCKS_PER_IMG)    // 8192
#define RED_THREADS 256

#define APPLY_THREADS 256
#define APPLY_BLOCKS ((N_IMG * IMG_VEC4) / APPLY_THREADS)   // 49152

// Scratch (no allocations allowed)
__device__ float2 g_partials[N_IMG * BLOCKS_PER_IMG];
__device__ float2 g_scale_shift[N_IMG];   // (scale, shift)

// -------- Kernel 1: per-chunk partial (sum, sumsq); fills L2 front-to-back --------
__global__ __launch_bounds__(RED_THREADS)
void partial_reduce_kernel(const float4* __restrict__ in) {
    const int img   = blockIdx.x / BLOCKS_PER_IMG;
    const int chunk = blockIdx.x % BLOCKS_PER_IMG;
    const float4* __restrict__ p =
        in + (size_t)img * IMG_VEC4 + (size_t)chunk * CHUNK_VEC4;

    float s = 0.f, sq = 0.f;
    #pragma unroll 8
    for (int i = threadIdx.x; i < CHUNK_VEC4; i += RED_THREADS) {
        float4 v = __ldcg(p + i);          // L2-cached, bypass L1
        s  += (v.x + v.y) + (v.z + v.w);
        sq += (v.x * v.x + v.y * v.y) + (v.z * v.z + v.w * v.w);
    }

    #pragma unroll
    for (int off = 16; off > 0; off >>= 1) {
        s  += __shfl_down_sync(0xffffffffu, s,  off);
        sq += __shfl_down_sync(0xffffffffu, sq, off);
    }
    __shared__ float2 warp_red[RED_THREADS / 32];
    const int lane = threadIdx.x & 31, wid = threadIdx.x >> 5;
    if (lane == 0) warp_red[wid] = make_float2(s, sq);
    __syncthreads();
    if (wid == 0) {
        float2 v = (lane < RED_THREADS / 32) ? warp_red[lane] : make_float2(0.f, 0.f);
        s = v.x; sq = v.y;
        #pragma unroll
        for (int off = 4; off > 0; off >>= 1) {
            s  += __shfl_down_sync(0xffffffffu, s,  off);
            sq += __shfl_down_sync(0xffffffffu, sq, off);
        }
        if (lane == 0) g_partials[blockIdx.x] = make_float2(s, sq);
    }
}

// -------- Kernel 2: finalize stats -> (scale, shift) per image --------
__global__ void finalize_kernel() {
    const int img  = blockIdx.x;
    const int lane = threadIdx.x;  // 32 threads
    float s = 0.f, sq = 0.f;
    if (lane < BLOCKS_PER_IMG) {
        float2 v = g_partials[img * BLOCKS_PER_IMG + lane];
        s = v.x; sq = v.y;
    }
    #pragma unroll
    for (int off = 16; off > 0; off >>= 1) {
        s  += __shfl_down_sync(0xffffffffu, s,  off);
        sq += __shfl_down_sync(0xffffffffu, sq, off);
    }
    if (lane == 0) {
        const float inv_n = 1.0f / (float)IMG_ELEMS;
        float mean = s * inv_n;
        float var  = sq * inv_n - mean * mean;
        float stddev = sqrtf(fmaxf(var, 0.0f));
        const float min_std = 1.0f / sqrtf((float)IMG_ELEMS);
        float adj = fmaxf(stddev, min_std);
        float scale = 1.0f / adj;
        g_scale_shift[img] = make_float2(scale, -mean * scale);
    }
}

// -------- Kernel 3: apply, blocks mapped tail-first to harvest L2 residue --------
__global__ __launch_bounds__(APPLY_THREADS)
void apply_kernel(const float4* __restrict__ in, float4* __restrict__ out) {
    // Mirror the block mapping: first-scheduled blocks touch the highest
    // addresses (most recently streamed through L2 by kernel 1).
    const unsigned rblk = (APPLY_BLOCKS - 1u) - blockIdx.x;
    const unsigned idx  = rblk * APPLY_THREADS + threadIdx.x;  // ascending within block
    const unsigned img  = idx / IMG_VEC4;
    const float2 ss = g_scale_shift[img];
    float4 v = __ldcg(in + idx);           // hit L2 where resident
    float4 r;
    r.x = fmaf(v.x, ss.x, ss.y);
    r.y = fmaf(v.y, ss.x, ss.y);
    r.z = fmaf(v.z, ss.x, ss.y);
    r.w = fmaf(v.w, ss.x, ss.y);
    __stcs(out + idx, r);                  // evict-first store: keep L2 for reads
}

extern "C" void kernel_launch(void* const* d_in, const int* in_sizes, int n_in,
                              void* d_out, int out_size) {
    const float4* in = (const float4*)d_in[0];
    float4* out = (float4*)d_out;

    partial_reduce_kernel<<<N_IMG * BLOCKS_PER_IMG, RED_THREADS>>>(in);
    finalize_kernel<<<N_IMG, 32>>>();
    apply_kernel<<<APPLY_BLOCKS, APPLY_THREADS>>>(in, out);
}

// round 6
// speedup vs baseline: 1.3288x; 1.0266x over previous
#include <cuda_runtime.h>
#include <math.h>

// Geometry: 64 images of 512*512*3 = 786432 floats (3 MB each)
#define N_IMG 64
#define IMG_ELEMS 786432
#define IMG_VEC4  196608               // IMG_ELEMS / 4
#define BLOCKS_PER_IMG 24
#define CHUNK_VEC4 (IMG_VEC4 / BLOCKS_PER_IMG)    // 8192
#define RED_THREADS 256

#define APPLY_THREADS 256
#define V4_PER_THREAD 4
#define V4_PER_BLOCK (APPLY_THREADS * V4_PER_THREAD)         // 4096
#define APPLY_BLOCKS ((N_IMG * IMG_VEC4) / V4_PER_BLOCK)     // 3072
#define APPLY_BLOCKS_PER_IMG (IMG_VEC4 / V4_PER_BLOCK)       // 48

// Scratch (no allocations allowed)
__device__ float2 g_partials[N_IMG * BLOCKS_PER_IMG];

// -------- Kernel 1: per-chunk partial (sum, sumsq); fills L2 front-to-back --------
__global__ __launch_bounds__(RED_THREADS)
void partial_reduce_kernel(const float4* __restrict__ in) {
    const int img   = blockIdx.x / BLOCKS_PER_IMG;
    const int chunk = blockIdx.x % BLOCKS_PER_IMG;
    const float4* __restrict__ p =
        in + (size_t)img * IMG_VEC4 + (size_t)chunk * CHUNK_VEC4;

    float s = 0.f, sq = 0.f;
    #pragma unroll 8
    for (int i = threadIdx.x; i < CHUNK_VEC4; i += RED_THREADS) {
        float4 v = __ldcg(p + i);          // cache in L2 (we re-read in apply)
        s  += (v.x + v.y) + (v.z + v.w);
        sq += (v.x * v.x + v.y * v.y) + (v.z * v.z + v.w * v.w);
    }

    #pragma unroll
    for (int off = 16; off > 0; off >>= 1) {
        s  += __shfl_down_sync(0xffffffffu, s,  off);
        sq += __shfl_down_sync(0xffffffffu, sq, off);
    }
    __shared__ float2 warp_red[RED_THREADS / 32];
    const int lane = threadIdx.x & 31, wid = threadIdx.x >> 5;
    if (lane == 0) warp_red[wid] = make_float2(s, sq);
    __syncthreads();
    if (wid == 0) {
        float2 v = (lane < RED_THREADS / 32) ? warp_red[lane] : make_float2(0.f, 0.f);
        s = v.x; sq = v.y;
        #pragma unroll
        for (int off = 4; off > 0; off >>= 1) {
            s  += __shfl_down_sync(0xffffffffu, s,  off);
            sq += __shfl_down_sync(0xffffffffu, sq, off);
        }
        if (lane == 0) g_partials[blockIdx.x] = make_float2(s, sq);
    }
}

// -------- Kernel 2: apply with inline per-block finalize --------
// Blocks mapped tail-first to harvest L2 residue from kernel 1.
// All memory ops are evict-first (.cs): each line is touched exactly once,
// so caching the fills would only evict the resident tail.
__global__ __launch_bounds__(APPLY_THREADS)
void apply_kernel(const float4* __restrict__ in, float4* __restrict__ out) {
    const unsigned rblk = (APPLY_BLOCKS - 1u) - blockIdx.x;
    const unsigned img  = rblk / APPLY_BLOCKS_PER_IMG;
    const size_t   base = (size_t)rblk * V4_PER_BLOCK + threadIdx.x;

    // Front-batch the loads (long latency, maximize MLP)
    float4 v[V4_PER_THREAD];
    #pragma unroll
    for (int k = 0; k < V4_PER_THREAD; ++k)
        v[k] = __ldcs(in + base + k * APPLY_THREADS);

    // Inline finalize: warp 0 reduces this image's 24 partials (fixed order
    // tree -> deterministic and identical across all blocks of the image).
    __shared__ float2 sh_ss;
    if (threadIdx.x < 32) {
        const int lane = threadIdx.x;
        float s = 0.f, sq = 0.f;
        if (lane < BLOCKS_PER_IMG) {
            float2 p = g_partials[img * BLOCKS_PER_IMG + lane];
            s = p.x; sq = p.y;
        }
        #pragma unroll
        for (int off = 16; off > 0; off >>= 1) {
            s  += __shfl_down_sync(0xffffffffu, s,  off);
            sq += __shfl_down_sync(0xffffffffu, sq, off);
        }
        if (lane == 0) {
            const float inv_n = 1.0f / (float)IMG_ELEMS;
            float mean = s * inv_n;
            float var  = sq * inv_n - mean * mean;
            float stddev = sqrtf(fmaxf(var, 0.0f));
            const float min_std = 1.0f / sqrtf((float)IMG_ELEMS);
            float scale = 1.0f / fmaxf(stddev, min_std);
            sh_ss = make_float2(scale, -mean * scale);
        }
    }
    __syncthreads();
    const float scale = sh_ss.x, shift = sh_ss.y;

    #pragma unroll
    for (int k = 0; k < V4_PER_THREAD; ++k) {
        float4 r;
        r.x = fmaf(v[k].x, scale, shift);
        r.y = fmaf(v[k].y, scale, shift);
        r.z = fmaf(v[k].z, scale, shift);
        r.w = fmaf(v[k].w, scale, shift);
        __stcs(out + base + k * APPLY_THREADS, r);
    }
}

extern "C" void kernel_launch(void* const* d_in, const int* in_sizes, int n_in,
                              void* d_out, int out_size) {
    const float4* in = (const float4*)d_in[0];
    float4* out = (float4*)d_out;

    partial_reduce_kernel<<<N_IMG * BLOCKS_PER_IMG, RED_THREADS>>>(in);
    apply_kernel<<<APPLY_BLOCKS, APPLY_THREADS>>>(in, out);
}